// round 5
// baseline (speedup 1.0000x reference)
#include <cuda_runtime.h>
#include <stdint.h>

// out[b, p, i] = state_p[b, rev12(i)],  rev12 = 12-bit bit reversal.
// Tile decomposition: r = u*128 + t*32 + v  (u,v in [0,32), t in [0,4))
//                 =>  i = rev5(v)*128 + rev2(t)*32 + rev5(u)
// One 256-thread CTA per (b, part, tile-pair): grid 1024, 8 CTAs/SM.
// Phase 1: cp.async.cg 16B global->shared with swizzled dst (no register
//          staging, single group-wait). Phase 2: conflict-free scalar LDS
//          gather + coalesced STG.128.
// smem layout tile[u*32 + (v ^ ((u&7)<<2))]: XORs only bits 2..4 of v, so
// 16B float4s stay intact; both phases are 32-bank conflict-free (bijective
// GF(2) lane->bank maps, verified rounds 3-4).

#define NSTATE  4096
#define THREADS 256

__device__ __forceinline__ int rev5(int v) { return (int)(__brev((unsigned)v) >> 27); }
__device__ __forceinline__ int rev3(int v) { return (int)(__brev((unsigned)v) >> 29); }

__device__ __forceinline__ void cp_async16(float* smem_dst, const float* gmem_src)
{
    unsigned saddr = (unsigned)__cvta_generic_to_shared(smem_dst);
    asm volatile("cp.async.cg.shared.global [%0], [%1], 16;\n"
                 :: "r"(saddr), "l"(gmem_src));
}

__global__ __launch_bounds__(THREADS)
void qft_bitrev_async_kernel(const float* __restrict__ state_real,
                             const float* __restrict__ state_imag,
                             float* __restrict__ out)
{
    __shared__ float tile[2][1024];

    const int c    = blockIdx.x;      // 0..1023: (b*2+part)*2 + half
    const int half = c & 1;           // which tile pair: t in {2*half, 2*half+1}
    const int bp   = c >> 1;          // vector index b*2+part
    const int b    = bp >> 1;
    const int part = bp & 1;

    const float* __restrict__ src =
        ((part == 0) ? state_real : state_imag) + (size_t)b * NSTATE;
    float* __restrict__ dst = out + (size_t)bp * NSTATE;   // [B,2,N,1] flat

    const int tid = threadIdx.x;
    const int u   = tid >> 3;         // 0..31
    const int x   = tid & 7;          // 0..7

    // Phase 1: async coalesced 16B loads, swizzled smem destinations.
    #pragma unroll
    for (int j = 0; j < 2; j++) {
        const int t = half * 2 + j;
        cp_async16(&tile[j][u * 32 + ((4 * x) ^ ((u & 7) << 2))],
                   src + u * 128 + t * 32 + 4 * x);
    }
    asm volatile("cp.async.commit_group;\n" ::: "memory");
    asm volatile("cp.async.wait_group 0;\n" ::: "memory");
    __syncthreads();

    // Phase 2: conflict-free LDS gather (the transpose), coalesced STG.128.
    // v = tid>>3, x = tid&7; component d reads u_d = rev3(x)+{0,16,8,24},
    // all sharing the same swizzle term -> one base + imm offsets.
    const int v  = u;                 // same decomposition, renamed role
    const int r3 = rev3(x);
    #pragma unroll
    for (int j = 0; j < 2; j++) {
        const int t  = half * 2 + j;
        const int rt = ((t & 1) << 1) | (t >> 1);   // rev2(t)
        const float* __restrict__ basep = &tile[j][r3 * 32 + (v ^ (r3 << 2))];
        float4 val;
        val.x = basep[0];
        val.y = basep[512];
        val.z = basep[256];
        val.w = basep[768];
        *reinterpret_cast<float4*>(dst + rev5(v) * 128 + rt * 32 + 4 * x) = val;
    }
}

extern "C" void kernel_launch(void* const* d_in, const int* in_sizes, int n_in,
                              void* d_out, int out_size)
{
    // metadata order: matrix (unused: it IS the 12-bit bit-reversal
    // permutation), state_real [256,4096,1], state_imag [256,4096,1]
    const float* state_real = (const float*)d_in[1];
    const float* state_imag = (const float*)d_in[2];
    float* out = (float*)d_out;

    const int batch = in_sizes[1] / NSTATE;   // 256
    qft_bitrev_async_kernel<<<batch * 2 * 2, THREADS>>>(state_real, state_imag, out);
}

// round 6
// speedup vs baseline: 1.0146x; 1.0146x over previous
#include <cuda_runtime.h>
#include <stdint.h>

// out[b, p, i] = state_p[b, rev12(i)],  rev12 = 12-bit bit reversal.
// Tile decomposition: r = u*128 + t*32 + v  (u,v in [0,32), t in [0,4))
//                 =>  i = rev5(v)*128 + rev2(t)*32 + rev5(u)
//
// Warp-autonomous version: each WARP owns one 1024-element tile end-to-end
// (8 float4 per thread). No __syncthreads — only cp.async.wait_group +
// __syncwarp (bar.warp.sync orders the async writes within the warp).
// 8 warps/CTA -> grid 256: minimal dispatch ramp, no barrier drain, warps
// retire independently (no wave-tail coupling).
//
// smem layout tile[u*32 + (v ^ ((u&7)<<2))]: XOR touches only bits 2..4 of v
// so 16B granules stay intact. Conflict-free both phases (GF(2) lane->bank
// maps bijective; re-verified for this lane decomposition). Both global
// sides fully 128B-coalesced.

#define NSTATE        4096
#define THREADS       256
#define WARPS_PER_CTA 8

__device__ __forceinline__ int rev5(int v) { return (int)(__brev((unsigned)v) >> 27); }
__device__ __forceinline__ int rev3(int v) { return (int)(__brev((unsigned)v) >> 29); }

__device__ __forceinline__ void cp_async16(float* smem_dst, const float* gmem_src)
{
    unsigned saddr = (unsigned)__cvta_generic_to_shared(smem_dst);
    asm volatile("cp.async.cg.shared.global [%0], [%1], 16;\n"
                 :: "r"(saddr), "l"(gmem_src));
}

__global__ __launch_bounds__(THREADS)
void qft_bitrev_warptile_kernel(const float* __restrict__ state_real,
                                const float* __restrict__ state_imag,
                                float* __restrict__ out)
{
    __shared__ float tiles[WARPS_PER_CTA][1024];

    const int wid  = threadIdx.x >> 5;
    const int lane = threadIdx.x & 31;

    const int g    = blockIdx.x * WARPS_PER_CTA + wid;  // tile id 0..2047
    const int t    = g & 3;
    const int bp   = g >> 2;                            // b*2 + part
    const int part = bp & 1;
    const int b    = bp >> 1;

    const float* __restrict__ src =
        ((part == 0) ? state_real : state_imag) + (size_t)b * NSTATE + t * 32;
    float* __restrict__ dst =
        out + (size_t)bp * NSTATE + ((((t & 1) << 1) | (t >> 1)) * 32);

    float* __restrict__ tile = tiles[wid];

    const int lu = lane >> 3;   // 0..3
    const int x  = lane & 7;    // 0..7

    // Phase 1: 8 async coalesced 16B loads per thread, swizzled smem dst.
    #pragma unroll
    for (int i = 0; i < 8; i++) {
        const int u = i * 4 + lu;
        cp_async16(&tile[u * 32 + ((4 * x) ^ ((u & 7) << 2))],
                   src + u * 128 + 4 * x);
    }
    asm volatile("cp.async.commit_group;\n" ::: "memory");
    asm volatile("cp.async.wait_group 0;\n" ::: "memory");
    __syncwarp();

    // Phase 2: conflict-free scalar LDS gather, coalesced STG.128.
    // v = i*4+lu; component d reads u_d = rev3(x)+{0,16,8,24}, all sharing
    // the same swizzle term -> one base + immediate offsets {0,512,256,768}.
    const int r3 = rev3(x);
    #pragma unroll
    for (int i = 0; i < 8; i++) {
        const int v = i * 4 + lu;
        const float* __restrict__ basep = &tile[r3 * 32 + (v ^ (r3 << 2))];
        float4 val;
        val.x = basep[0];
        val.y = basep[512];
        val.z = basep[256];
        val.w = basep[768];
        *reinterpret_cast<float4*>(dst + rev5(v) * 128 + 4 * x) = val;
    }
}

extern "C" void kernel_launch(void* const* d_in, const int* in_sizes, int n_in,
                              void* d_out, int out_size)
{
    // metadata order: matrix (unused: it IS the 12-bit bit-reversal
    // permutation), state_real [256,4096,1], state_imag [256,4096,1]
    const float* state_real = (const float*)d_in[1];
    const float* state_imag = (const float*)d_in[2];
    float* out = (float*)d_out;

    const int batch = in_sizes[1] / NSTATE;             // 256
    const int tiles = batch * 2 * 4;                    // 2048 warp-tiles
    qft_bitrev_warptile_kernel<<<tiles / WARPS_PER_CTA, THREADS>>>(
        state_real, state_imag, out);
}

// round 8
// speedup vs baseline: 1.0773x; 1.0619x over previous
#include <cuda_runtime.h>
#include <stdint.h>

// out[b, p, i] = state_p[b, rev12(i)],  rev12 = 12-bit bit reversal.
// Tile decomposition: r = u*128 + t*32 + v  (u,v in [0,32), t in [0,4))
//                 =>  i = rev5(v)*128 + rev2(t)*32 + rev5(u)
// Best-measured config (R3): one 128-thread CTA per (b,part,t) tile, grid 2048,
// combined with cp.async phase 1 (R5) and streaming .cs output stores (new):
// the output is write-once, so evict-first keeps the 8 MB input L2-resident.
//
// smem layout tile[u*32 + (v ^ ((u&7)<<2))]: XOR touches only bits 2..4 of v,
// so 16B granules stay intact (cp.async dst stays 16B-aligned). Both phases
// 32-bank conflict-free (bijective GF(2) lane->bank maps, verified R3-R6).
// Both global sides fully 128B-coalesced.

#define NSTATE  4096
#define THREADS 128

__device__ __forceinline__ int rev5(int v) { return (int)(__brev((unsigned)v) >> 27); }
__device__ __forceinline__ int rev3(int v) { return (int)(__brev((unsigned)v) >> 29); }

__device__ __forceinline__ void cp_async16(float* smem_dst, const float* gmem_src)
{
    unsigned saddr = (unsigned)__cvta_generic_to_shared(smem_dst);
    asm volatile("cp.async.cg.shared.global [%0], [%1], 16;\n"
                 :: "r"(saddr), "l"(gmem_src));
}

__global__ __launch_bounds__(THREADS)
void qft_bitrev_tile_cs_kernel(const float* __restrict__ state_real,
                               const float* __restrict__ state_imag,
                               float* __restrict__ out)
{
    __shared__ float tile[1024];

    const int blk  = blockIdx.x;          // b*8 + part*4 + t
    const int t    = blk & 3;
    const int part = (blk >> 2) & 1;
    const int b    = blk >> 3;

    const float* __restrict__ src =
        ((part == 0) ? state_real : state_imag) + (size_t)b * NSTATE + t * 32;
    float* __restrict__ dst =
        out + ((size_t)b * 2 + part) * NSTATE + ((((t & 1) << 1) | (t >> 1)) * 32);

    const int tid = threadIdx.x;

    // Phase 1: async coalesced 16B loads, swizzled smem destinations.
    // p in [0,256): u = p>>3, x = p&7
    #pragma unroll
    for (int q = 0; q < 2; q++) {
        const int p = tid + q * THREADS;
        const int u = p >> 3;
        const int x = p & 7;
        cp_async16(&tile[u * 32 + ((4 * x) ^ ((u & 7) << 2))],
                   src + u * 128 + 4 * x);
    }
    asm volatile("cp.async.commit_group;\n" ::: "memory");
    asm volatile("cp.async.wait_group 0;\n" ::: "memory");
    __syncthreads();

    // Phase 2: conflict-free scalar LDS gather (the transpose), streaming
    // STG.128 (.cs: output never re-read -> evict-first, protect L2 input).
    // v = p>>3, x = p&7; component d reads u_d = rev3(x)+{0,16,8,24}, all
    // sharing one swizzle term -> one base + immediate offsets.
    #pragma unroll
    for (int q = 0; q < 2; q++) {
        const int p  = tid + q * THREADS;
        const int v  = p >> 3;
        const int x  = p & 7;
        const int r3 = rev3(x);
        const float* __restrict__ basep = &tile[r3 * 32 + (v ^ (r3 << 2))];
        float4 val;
        val.x = basep[0];
        val.y = basep[512];
        val.z = basep[256];
        val.w = basep[768];
        __stcs(reinterpret_cast<float4*>(dst + rev5(v) * 128 + 4 * x), val);
    }
}

extern "C" void kernel_launch(void* const* d_in, const int* in_sizes, int n_in,
                              void* d_out, int out_size)
{
    // metadata order: matrix (unused: it IS the 12-bit bit-reversal
    // permutation), state_real [256,4096,1], state_imag [256,4096,1]
    const float* state_real = (const float*)d_in[1];
    const float* state_imag = (const float*)d_in[2];
    float* out = (float*)d_out;

    const int batch = in_sizes[1] / NSTATE;   // 256
    qft_bitrev_tile_cs_kernel<<<batch * 2 * 4, THREADS>>>(state_real, state_imag, out);
}

// round 9
// speedup vs baseline: 1.0942x; 1.0157x over previous
#include <cuda_runtime.h>
#include <stdint.h>

// out[b, p, i] = state_p[b, rev12(i)],  rev12 = 12-bit bit reversal.
// Tile decomposition: r = u*128 + t*32 + v  (u,v in [0,32), t in [0,4))
//                 =>  i = rev5(v)*128 + rev2(t)*32 + rev5(u)
//
// Pipelined version: each 128-thread CTA owns TWO tiles (grid 1024) with
// double-buffered cp.async groups. Both tiles' loads are issued up front;
// wait_group 1 overlaps tile-0's LDS/STG phase with tile-1's in-flight
// loads, halving the per-CTA dependency stall. Streaming .cs stores keep
// the L2-resident input from being displaced by the write-once output.
//
// smem layout tile[u*32 + (v ^ ((u&7)<<2))]: XOR touches only bits 2..4 of v,
// so 16B granules stay intact (cp.async dst 16B-aligned). Both phases
// 32-bank conflict-free (bijective GF(2) lane->bank maps, verified R3-R8).
// Both global sides fully 128B-coalesced.

#define NSTATE  4096
#define THREADS 128

__device__ __forceinline__ int rev5(int v) { return (int)(__brev((unsigned)v) >> 27); }
__device__ __forceinline__ int rev3(int v) { return (int)(__brev((unsigned)v) >> 29); }

__device__ __forceinline__ void cp_async16(float* smem_dst, const float* gmem_src)
{
    unsigned saddr = (unsigned)__cvta_generic_to_shared(smem_dst);
    asm volatile("cp.async.cg.shared.global [%0], [%1], 16;\n"
                 :: "r"(saddr), "l"(gmem_src));
}

__global__ __launch_bounds__(THREADS)
void qft_bitrev_pipe_kernel(const float* __restrict__ state_real,
                            const float* __restrict__ state_imag,
                            float* __restrict__ out)
{
    __shared__ float tiles[2][1024];

    const int c    = blockIdx.x;      // (b*2+part)*2 + half
    const int half = c & 1;           // tiles t = 2*half, 2*half+1
    const int bp   = c >> 1;          // b*2 + part
    const int part = bp & 1;
    const int b    = bp >> 1;

    const float* __restrict__ src =
        ((part == 0) ? state_real : state_imag) + (size_t)b * NSTATE;
    float* __restrict__ dst = out + (size_t)bp * NSTATE;   // [B,2,N,1] flat

    const int tid = threadIdx.x;

    // Issue BOTH tiles' loads up front, one commit group per tile.
    #pragma unroll
    for (int j = 0; j < 2; j++) {
        const int t = half * 2 + j;
        #pragma unroll
        for (int q = 0; q < 2; q++) {
            const int p = tid + q * THREADS;
            const int u = p >> 3;
            const int x = p & 7;
            cp_async16(&tiles[j][u * 32 + ((4 * x) ^ ((u & 7) << 2))],
                       src + u * 128 + t * 32 + 4 * x);
        }
        asm volatile("cp.async.commit_group;\n" ::: "memory");
    }

    // Drain tile j's group, then gather+store it while tile j+1 is in flight.
    #pragma unroll
    for (int j = 0; j < 2; j++) {
        if (j == 0) asm volatile("cp.async.wait_group 1;\n" ::: "memory");
        else        asm volatile("cp.async.wait_group 0;\n" ::: "memory");
        __syncthreads();

        const int t  = half * 2 + j;
        const int rt = ((t & 1) << 1) | (t >> 1);   // rev2(t)
        #pragma unroll
        for (int q = 0; q < 2; q++) {
            const int p  = tid + q * THREADS;
            const int v  = p >> 3;
            const int x  = p & 7;
            const int r3 = rev3(x);
            const float* __restrict__ basep = &tiles[j][r3 * 32 + (v ^ (r3 << 2))];
            float4 val;
            val.x = basep[0];
            val.y = basep[512];
            val.z = basep[256];
            val.w = basep[768];
            __stcs(reinterpret_cast<float4*>(dst + rev5(v) * 128 + rt * 32 + 4 * x), val);
        }
    }
}

extern "C" void kernel_launch(void* const* d_in, const int* in_sizes, int n_in,
                              void* d_out, int out_size)
{
    // metadata order: matrix (unused: it IS the 12-bit bit-reversal
    // permutation), state_real [256,4096,1], state_imag [256,4096,1]
    const float* state_real = (const float*)d_in[1];
    const float* state_imag = (const float*)d_in[2];
    float* out = (float*)d_out;

    const int batch = in_sizes[1] / NSTATE;   // 256
    qft_bitrev_pipe_kernel<<<batch * 2 * 2, THREADS>>>(state_real, state_imag, out);
}